// round 5
// baseline (speedup 1.0000x reference)
#include <cuda_runtime.h>
#include <cstdint>

// ---------------- problem constants ----------------
#define BATCH 256
#define HW    147456            // 384*384
#define NBF   65536             // fine histogram bins
#define NW    (NBF / 2)         // packed u32 words (2 x u16 counters) = 32768
#define TPB   1024
#define SMEM_HIST (NW * 4)      // 131072 bytes dynamic smem

// target order-statistic ranks (0-based): q*(n-1) = 14745.5 / 132709.5
#define KL 14745
#define KH 132709

// ---------------- device scratch (static, allocation-free) ----------------
__device__ float g_xg[BATCH * HW];   // channel-mean image, 151 MB

// ---------------- single fused kernel: one block per sample -----------------
__global__ void __launch_bounds__(TPB) fused(const float* __restrict__ x,
                                             float* __restrict__ out) {
    extern __shared__ uint32_t hist[];   // NW packed words
    __shared__ int   s_warp[32];
    __shared__ float s_vals[4];
    __shared__ float s_lo, s_inv;

    const int s = blockIdx.x;
    const int t = threadIdx.x;
    const int lane = t & 31;
    const int wid  = t >> 5;

    // ---- phase 0: zero histogram ----
#pragma unroll 8
    for (int i = t; i < NW; i += TPB) hist[i] = 0u;
    __syncthreads();

    // ---- phase 1: stream x, compute channel mean, write xg, histogram ----
    const float4* __restrict__ xin = (const float4*)x + (size_t)s * (HW * 3 / 4);
    float4* __restrict__ xg4 = (float4*)g_xg + (size_t)s * (HW / 4);
    const float third = 1.0f / 3.0f;

#pragma unroll 4
    for (int i = t; i < HW / 4; i += TPB) {
        float4 a = __ldcs(xin + i * 3 + 0);   // stream: don't pollute L2
        float4 b = __ldcs(xin + i * 3 + 1);
        float4 c = __ldcs(xin + i * 3 + 2);

        float m0 = (a.x + a.y + a.z) * third;
        float m1 = (a.w + b.x + b.y) * third;
        float m2 = (b.z + b.w + c.x) * third;
        float m3 = (c.y + c.z + c.w) * third;

        float4 o; o.x = m0; o.y = m1; o.z = m2; o.w = m3;
        xg4[i] = o;                            // default store: retain in L2

        int b0 = min((int)(m0 * (float)NBF), NBF - 1);
        int b1 = min((int)(m1 * (float)NBF), NBF - 1);
        int b2 = min((int)(m2 * (float)NBF), NBF - 1);
        int b3 = min((int)(m3 * (float)NBF), NBF - 1);
        // packed u16 counters: two bins per u32 word
        atomicAdd(&hist[b0 >> 1], 1u << ((b0 & 1) << 4));
        atomicAdd(&hist[b1 >> 1], 1u << ((b1 & 1) << 4));
        atomicAdd(&hist[b2 >> 1], 1u << ((b2 & 1) << 4));
        atomicAdd(&hist[b3 >> 1], 1u << ((b3 & 1) << 4));
    }
    __syncthreads();

    // ---- phase 2: block-wide scan over 65536 bins, locate+interpolate ranks --
    {
        const int W = NW / TPB;   // 32 words (64 bins) per thread
        const int base = t * W;

        int local = 0;
#pragma unroll
        for (int j = 0; j < W; j++) {
            uint32_t w = hist[base + j];
            local += (int)(w & 0xFFFFu) + (int)(w >> 16);
        }

        // warp inclusive scan
        int v = local;
#pragma unroll
        for (int o = 1; o < 32; o <<= 1) {
            int n = __shfl_up_sync(0xFFFFFFFFu, v, o);
            if (lane >= o) v += n;
        }
        if (lane == 31) s_warp[wid] = v;
        __syncthreads();
        if (wid == 0) {
            int wv = s_warp[lane];
#pragma unroll
            for (int o = 1; o < 32; o <<= 1) {
                int n = __shfl_up_sync(0xFFFFFFFFu, wv, o);
                if (lane >= o) wv += n;
            }
            s_warp[lane] = wv;
        }
        __syncthreads();
        // exclusive prefix (count of values strictly before this thread's bins)
        int cum = (v - local) + (wid ? s_warp[wid - 1] : 0);

        const int targets[4] = {KL, KL + 1, KH, KH + 1};
        const float invNBF = 1.0f / (float)NBF;
#pragma unroll 8
        for (int j = 0; j < W; j++) {
            uint32_t w = hist[base + j];
            int c0 = (int)(w & 0xFFFFu);
            int c1 = (int)(w >> 16);
            int bin0 = (base + j) * 2;
#pragma unroll
            for (int k = 0; k < 4; k++) {
                int r = targets[k];
                if (cum <= r && r < cum + c0)
                    s_vals[k] = ((float)bin0 + ((float)(r - cum) + 0.5f) / (float)c0) * invNBF;
            }
            cum += c0;
#pragma unroll
            for (int k = 0; k < 4; k++) {
                int r = targets[k];
                if (cum <= r && r < cum + c1)
                    s_vals[k] = ((float)(bin0 + 1) + ((float)(r - cum) + 0.5f) / (float)c1) * invNBF;
            }
            cum += c1;
        }
    }
    __syncthreads();

    if (t == 0) {
        float lo = 0.5f * (s_vals[0] + s_vals[1]);
        float hi = 0.5f * (s_vals[2] + s_vals[3]);
        float rng = fmaxf(hi - lo, 1e-6f);
        s_lo  = lo;
        s_inv = 1.0f / rng;
    }
    __syncthreads();

    // ---- phase 3: normalize + clip (xg re-read is L2-hot: 85 MB resident) ----
    const float lo  = s_lo;
    const float inv = s_inv;
    float4* __restrict__ o4 = (float4*)out + (size_t)s * (HW / 4);

#pragma unroll 4
    for (int i = t; i < HW / 4; i += TPB) {
        float4 v = __ldcs(xg4 + i);     // last use: evict-first
        float4 r;
        r.x = __saturatef((v.x - lo) * inv);
        r.y = __saturatef((v.y - lo) * inv);
        r.z = __saturatef((v.z - lo) * inv);
        r.w = __saturatef((v.w - lo) * inv);
        __stcs(o4 + i, r);              // streaming store
    }
}

// ---------------- launch ----------------
extern "C" void kernel_launch(void* const* d_in, const int* in_sizes, int n_in,
                              void* d_out, int out_size) {
    const float* x = (const float*)d_in[0];
    float* out = (float*)d_out;

    cudaFuncSetAttribute(fused, cudaFuncAttributeMaxDynamicSharedMemorySize, SMEM_HIST);
    fused<<<BATCH, TPB, SMEM_HIST>>>(x, out);
}

// round 6
// speedup vs baseline: 1.0043x; 1.0043x over previous
#include <cuda_runtime.h>
#include <cstdint>

// ---------------- problem constants ----------------
#define BATCH 256
#define HW    147456            // 384*384 pixels per sample
#define NB    4096              // coarse histogram bins
#define TPB   1024
#define F4    (HW / 4)          // 36864 float4 (means) per sample
#define ITERS (F4 / TPB)        // 36 float4 per thread
#define SMI   24                // iterations whose values live in shared memory
#define RGI   (ITERS - SMI)     // 12 iterations whose values live in registers
#define PLANE (SMI * TPB)       // words per smem plane (24576)
#define CAP   1024              // candidate capacity per quantile
#define QSCALE 65535.0f

// target order-statistic ranks (0-based): q*(n-1) = 14745.5 / 132709.5
#define KL 14745
#define KH 132709

#define DYN_SMEM (2 * PLANE * 4)   // 196608 B of packed u16 values

// One block per sample. Entire pipeline on-chip; DRAM = read x + write out only.
__global__ void __launch_bounds__(TPB) fused(const float* __restrict__ x,
                                             float* __restrict__ out) {
    extern __shared__ uint32_t val[];          // [2][PLANE] packed 2xu16 means
    __shared__ uint32_t hist[NB];              // 16 KB coarse histogram
    __shared__ uint16_t candLo[CAP], candHi[CAP];
    __shared__ int s_warp[32];
    __shared__ int s_selBin[4], s_selCum[4];   // bins/cums for ranks KL,KL+1,KH,KH+1
    __shared__ int cLo, cHi;
    __shared__ int s_res[4];
    __shared__ float s_loS, s_invS;

    const int s = blockIdx.x;
    const int t = threadIdx.x;
    const int lane = t & 31;
    const int wid  = t >> 5;

    for (int i = t; i < NB; i += TPB) hist[i] = 0u;
    if (t == 0) { cLo = 0; cHi = 0; }
    __syncthreads();

    // ---- phase 1: stream x, mean, quantize u16, store on-chip, histogram ----
    const float4* __restrict__ xin = (const float4*)x + (size_t)s * (3 * F4);
    const float third = 1.0f / 3.0f;
    uint32_t rv[RGI * 2];

#pragma unroll 4
    for (int k = 0; k < SMI; k++) {
        int i = k * TPB + t;
        float4 a = __ldcs(xin + 3 * i + 0);
        float4 b = __ldcs(xin + 3 * i + 1);
        float4 c = __ldcs(xin + 3 * i + 2);
        uint32_t q0 = (uint32_t)((a.x + a.y + a.z) * third * QSCALE + 0.5f);
        uint32_t q1 = (uint32_t)((a.w + b.x + b.y) * third * QSCALE + 0.5f);
        uint32_t q2 = (uint32_t)((b.z + b.w + c.x) * third * QSCALE + 0.5f);
        uint32_t q3 = (uint32_t)((c.y + c.z + c.w) * third * QSCALE + 0.5f);
        val[k * TPB + t]         = q0 | (q1 << 16);
        val[PLANE + k * TPB + t] = q2 | (q3 << 16);
        atomicAdd(&hist[q0 >> 4], 1u);
        atomicAdd(&hist[q1 >> 4], 1u);
        atomicAdd(&hist[q2 >> 4], 1u);
        atomicAdd(&hist[q3 >> 4], 1u);
    }
#pragma unroll
    for (int kk = 0; kk < RGI; kk++) {
        int i = (SMI + kk) * TPB + t;
        float4 a = __ldcs(xin + 3 * i + 0);
        float4 b = __ldcs(xin + 3 * i + 1);
        float4 c = __ldcs(xin + 3 * i + 2);
        uint32_t q0 = (uint32_t)((a.x + a.y + a.z) * third * QSCALE + 0.5f);
        uint32_t q1 = (uint32_t)((a.w + b.x + b.y) * third * QSCALE + 0.5f);
        uint32_t q2 = (uint32_t)((b.z + b.w + c.x) * third * QSCALE + 0.5f);
        uint32_t q3 = (uint32_t)((c.y + c.z + c.w) * third * QSCALE + 0.5f);
        rv[2 * kk]     = q0 | (q1 << 16);
        rv[2 * kk + 1] = q2 | (q3 << 16);
        atomicAdd(&hist[q0 >> 4], 1u);
        atomicAdd(&hist[q1 >> 4], 1u);
        atomicAdd(&hist[q2 >> 4], 1u);
        atomicAdd(&hist[q3 >> 4], 1u);
    }
    __syncthreads();

    // ---- phase 2: block scan over 4096 bins, locate target-rank bins ----
    {
        const int base = t * 4;
        int c0 = hist[base], c1 = hist[base + 1], c2 = hist[base + 2], c3 = hist[base + 3];
        int local = c0 + c1 + c2 + c3;

        int v = local;
#pragma unroll
        for (int o = 1; o < 32; o <<= 1) {
            int n = __shfl_up_sync(0xFFFFFFFFu, v, o);
            if (lane >= o) v += n;
        }
        if (lane == 31) s_warp[wid] = v;
        __syncthreads();
        if (wid == 0) {
            int wv = s_warp[lane];
#pragma unroll
            for (int o = 1; o < 32; o <<= 1) {
                int n = __shfl_up_sync(0xFFFFFFFFu, wv, o);
                if (lane >= o) wv += n;
            }
            s_warp[lane] = wv;
        }
        __syncthreads();
        int cum = (v - local) + (wid ? s_warp[wid - 1] : 0);

        const int targets[4] = {KL, KL + 1, KH, KH + 1};
        int cnt[4] = {c0, c1, c2, c3};
#pragma unroll
        for (int i = 0; i < 4; i++) {
            int c = cnt[i];
#pragma unroll
            for (int k = 0; k < 4; k++) {
                int r = targets[k];
                if (cum <= r && r < cum + c) { s_selBin[k] = base + i; s_selCum[k] = cum; }
            }
            cum += c;
        }
    }
    __syncthreads();

    // ---- phase 3: gather candidates from on-chip values ----
    const int bL0 = s_selBin[0], bL1 = s_selBin[1];
    const int bH0 = s_selBin[2], bH1 = s_selBin[3];
    {
#pragma unroll 4
        for (int k = 0; k < SMI; k++) {
            uint32_t p0 = val[k * TPB + t];
            uint32_t p1 = val[PLANE + k * TPB + t];
            uint32_t qs[4] = {p0 & 0xFFFFu, p0 >> 16, p1 & 0xFFFFu, p1 >> 16};
#pragma unroll
            for (int j = 0; j < 4; j++) {
                int b = (int)(qs[j] >> 4);
                if (b >= bL0 && b <= bL1) {
                    int idx = atomicAdd(&cLo, 1);
                    if (idx < CAP) candLo[idx] = (uint16_t)qs[j];
                }
                if (b >= bH0 && b <= bH1) {
                    int idx = atomicAdd(&cHi, 1);
                    if (idx < CAP) candHi[idx] = (uint16_t)qs[j];
                }
            }
        }
#pragma unroll
        for (int kk = 0; kk < RGI; kk++) {
            uint32_t p0 = rv[2 * kk], p1 = rv[2 * kk + 1];
            uint32_t qs[4] = {p0 & 0xFFFFu, p0 >> 16, p1 & 0xFFFFu, p1 >> 16};
#pragma unroll
            for (int j = 0; j < 4; j++) {
                int b = (int)(qs[j] >> 4);
                if (b >= bL0 && b <= bL1) {
                    int idx = atomicAdd(&cLo, 1);
                    if (idx < CAP) candLo[idx] = (uint16_t)qs[j];
                }
                if (b >= bH0 && b <= bH1) {
                    int idx = atomicAdd(&cHi, 1);
                    if (idx < CAP) candHi[idx] = (uint16_t)qs[j];
                }
            }
        }
    }
    __syncthreads();

    // ---- phase 4: exact counting-rank selection on u16 candidates ----
    for (int q = 0; q < 2; q++) {
        const uint16_t* sv = q ? candHi : candLo;
        int n  = min(q ? cHi : cLo, CAP);
        int t0 = (q ? KH : KL) - s_selCum[q ? 2 : 0];
        for (int i = t; i < n; i += TPB) {
            int v = sv[i];
            int L = 0, E = 0;
            for (int j = 0; j < n; j++) {
                int u = sv[j];
                L += (u < v);
                E += (u == v);
            }
            if (L <= t0     && t0     < L + E) s_res[2 * q]     = v;
            if (L <= t0 + 1 && t0 + 1 < L + E) s_res[2 * q + 1] = v;
        }
    }
    __syncthreads();

    if (t == 0) {
        // lo/hi in quantized units; fold dequant scale into the affine map
        float loQ = 0.5f * (float)(s_res[0] + s_res[1]);   // in [0, 65535]
        float hiQ = 0.5f * (float)(s_res[2] + s_res[3]);
        float rngQ = fmaxf((hiQ - loQ), 1e-6f * QSCALE);
        s_loS  = loQ;
        s_invS = 1.0f / rngQ;
    }
    __syncthreads();

    // ---- phase 5: normalize + clip from on-chip values, stream out ----
    const float loS  = s_loS;
    const float invS = s_invS;
    float4* __restrict__ o4 = (float4*)out + (size_t)s * F4;

#pragma unroll 4
    for (int k = 0; k < SMI; k++) {
        uint32_t p0 = val[k * TPB + t];
        uint32_t p1 = val[PLANE + k * TPB + t];
        float4 r;
        r.x = __saturatef(((float)(p0 & 0xFFFFu) - loS) * invS);
        r.y = __saturatef(((float)(p0 >> 16)     - loS) * invS);
        r.z = __saturatef(((float)(p1 & 0xFFFFu) - loS) * invS);
        r.w = __saturatef(((float)(p1 >> 16)     - loS) * invS);
        __stcs(o4 + k * TPB + t, r);
    }
#pragma unroll
    for (int kk = 0; kk < RGI; kk++) {
        uint32_t p0 = rv[2 * kk], p1 = rv[2 * kk + 1];
        float4 r;
        r.x = __saturatef(((float)(p0 & 0xFFFFu) - loS) * invS);
        r.y = __saturatef(((float)(p0 >> 16)     - loS) * invS);
        r.z = __saturatef(((float)(p1 & 0xFFFFu) - loS) * invS);
        r.w = __saturatef(((float)(p1 >> 16)     - loS) * invS);
        __stcs(o4 + (SMI + kk) * TPB + t, r);
    }
}

// ---------------- launch ----------------
extern "C" void kernel_launch(void* const* d_in, const int* in_sizes, int n_in,
                              void* d_out, int out_size) {
    const float* x = (const float*)d_in[0];
    float* out = (float*)d_out;

    cudaFuncSetAttribute(fused, cudaFuncAttributeMaxDynamicSharedMemorySize, DYN_SMEM);
    fused<<<BATCH, TPB, DYN_SMEM>>>(x, out);
}

// round 7
// speedup vs baseline: 1.1065x; 1.1018x over previous
#include <cuda_runtime.h>
#include <cstdint>

// ---------------- problem constants ----------------
#define BATCH 256
#define HW    147456            // 384*384 px per sample
#define NB    4096              // coarse histogram bins (bin = q >> 4)
#define QSCALE 65535.0f

// target order-statistic ranks (0-based): q*(n-1) = 14745.5 / 132709.5
#define KL 14745
#define KH 132709

// K1 geometry: 4 blocks/sample, 1024 threads, 36 px/thread
#define TPB1   1024
#define BPS1   4
#define PXB1   (HW / BPS1)            // 36864 px per block
#define ITER1  (PXB1 / (TPB1 * 4))    // 9 iterations of 4 px

// K2 geometry: 1 block/sample, 1024 threads, 36 slots of 4 px each
#define TPB2   1024
#define SLOTS  (HW / 4 / TPB2)        // 36 uint2 slots per thread
#define SMI    24                     // slots kept in shared memory
#define RGI    (SLOTS - SMI)          // 12 slots kept in registers
#define PLANE  (SMI * TPB2)           // 24576 words per smem plane
#define DYN_SMEM (2 * PLANE * 4)      // 196608 B
#define CAP    2048                   // candidate capacity per quantile

// ---------------- device scratch (static, allocation-free, zero-init) -------
__device__ uint32_t g_xq[BATCH * HW / 2];   // packed u16 means, 75 MB
__device__ int      g_hist[BATCH * NB];     // per-sample hist (self-cleaned by K2)

// ---- K1: stream x, channel-mean, quantize u16, write xq, histogram ---------
__global__ void __launch_bounds__(TPB1) k1_quant_hist(const float* __restrict__ x) {
    __shared__ int sh[NB];
    const int s     = blockIdx.x >> 2;        // / BPS1
    const int chunk = blockIdx.x & (BPS1 - 1);
    const int t     = threadIdx.x;

    for (int i = t; i < NB; i += TPB1) sh[i] = 0;
    __syncthreads();

    const int base = s * HW + chunk * PXB1;
    const float4* __restrict__ xin = (const float4*)x;
    const float third = 1.0f / 3.0f;

#pragma unroll 3
    for (int it = 0; it < ITER1; ++it) {
        int p  = base + it * (TPB1 * 4) + t * 4;   // global px (mult of 4)
        int f4 = (p * 3) >> 2;
        float4 a = __ldcs(xin + f4 + 0);   // stream x: don't pollute L2
        float4 b = __ldcs(xin + f4 + 1);
        float4 c = __ldcs(xin + f4 + 2);

        uint32_t q0 = min((uint32_t)((a.x + a.y + a.z) * third * QSCALE + 0.5f), 65535u);
        uint32_t q1 = min((uint32_t)((a.w + b.x + b.y) * third * QSCALE + 0.5f), 65535u);
        uint32_t q2 = min((uint32_t)((b.z + b.w + c.x) * third * QSCALE + 0.5f), 65535u);
        uint32_t q3 = min((uint32_t)((c.y + c.z + c.w) * third * QSCALE + 0.5f), 65535u);

        uint2 w; w.x = q0 | (q1 << 16); w.y = q2 | (q3 << 16);
        ((uint2*)g_xq)[p >> 2] = w;        // default store: retain in L2 for K2

        atomicAdd(&sh[q0 >> 4], 1);
        atomicAdd(&sh[q1 >> 4], 1);
        atomicAdd(&sh[q2 >> 4], 1);
        atomicAdd(&sh[q3 >> 4], 1);
    }
    __syncthreads();

    int* gh = &g_hist[s * NB];
    for (int i = t; i < NB; i += TPB1) {
        int v = sh[i];
        if (v) atomicAdd(&gh[i], v);       // result unused -> REDG
    }
}

// ---- K2: hist scan -> load xq on-chip + gather -> select -> normalize ------
__global__ void __launch_bounds__(TPB2) k2_select_norm(float* __restrict__ out) {
    extern __shared__ uint32_t sval[];       // [2][PLANE] packed u16 values
    __shared__ int s_warp[32];
    __shared__ int s_selBin[4], s_selCum[4];
    __shared__ uint16_t candLo[CAP], candHi[CAP];
    __shared__ int cLo, cHi;
    __shared__ int s_res[4];
    __shared__ float s_loS, s_invS;

    const int s = blockIdx.x;
    const int t = threadIdx.x;
    const int lane = t & 31;
    const int wid  = t >> 5;

    if (t == 0) { cLo = 0; cHi = 0; }

    // ---- phase A: read global hist (4 bins/thread), self-clean, scan ----
    {
        int* gh = &g_hist[s * NB];
        int4 cw = *(int4*)(gh + 4 * t);
        *(int4*)(gh + 4 * t) = make_int4(0, 0, 0, 0);   // self-clean for replay
        int c0 = cw.x, c1 = cw.y, c2 = cw.z, c3 = cw.w;
        int local = c0 + c1 + c2 + c3;

        int v = local;
#pragma unroll
        for (int o = 1; o < 32; o <<= 1) {
            int n = __shfl_up_sync(0xFFFFFFFFu, v, o);
            if (lane >= o) v += n;
        }
        if (lane == 31) s_warp[wid] = v;
        __syncthreads();
        if (wid == 0) {
            int wv = s_warp[lane];
#pragma unroll
            for (int o = 1; o < 32; o <<= 1) {
                int n = __shfl_up_sync(0xFFFFFFFFu, wv, o);
                if (lane >= o) wv += n;
            }
            s_warp[lane] = wv;
        }
        __syncthreads();
        int cum = (v - local) + (wid ? s_warp[wid - 1] : 0);

        const int targets[4] = {KL, KL + 1, KH, KH + 1};
        int cnt[4] = {c0, c1, c2, c3};
#pragma unroll
        for (int i = 0; i < 4; i++) {
            int c = cnt[i];
#pragma unroll
            for (int k = 0; k < 4; k++) {
                int r = targets[k];
                if (cum <= r && r < cum + c) { s_selBin[k] = 4 * t + i; s_selCum[k] = cum; }
            }
            cum += c;
        }
    }
    __syncthreads();

    // q-value gather windows (inclusive), derived from coarse bins
    const uint32_t qL0 = (uint32_t)(s_selBin[0] << 4);
    const uint32_t qL1 = (uint32_t)((s_selBin[1] << 4) | 15);
    const uint32_t qH0 = (uint32_t)(s_selBin[2] << 4);
    const uint32_t qH1 = (uint32_t)((s_selBin[3] << 4) | 15);

    // ---- phase B: stream xq on-chip (smem + regs), gather candidates ----
    const uint2* __restrict__ xq2 = (const uint2*)g_xq + (size_t)s * (HW / 8) * 2;
    uint32_t rv[RGI * 2];

#pragma unroll 4
    for (int k = 0; k < SLOTS; k++) {
        int j = k * TPB2 + t;
        uint2 w = xq2[j];
        if (k < SMI) {
            sval[k * TPB2 + t]         = w.x;
            sval[PLANE + k * TPB2 + t] = w.y;
        } else {
            rv[2 * (k - SMI)]     = w.x;
            rv[2 * (k - SMI) + 1] = w.y;
        }
        uint32_t qs[4] = {w.x & 0xFFFFu, w.x >> 16, w.y & 0xFFFFu, w.y >> 16};
#pragma unroll
        for (int i = 0; i < 4; i++) {
            uint32_t q = qs[i];
            if (q >= qL0 && q <= qL1) {
                int idx = atomicAdd(&cLo, 1);
                if (idx < CAP) candLo[idx] = (uint16_t)q;
            }
            if (q >= qH0 && q <= qH1) {
                int idx = atomicAdd(&cHi, 1);
                if (idx < CAP) candHi[idx] = (uint16_t)q;
            }
        }
    }
    __syncthreads();

    // ---- phase C: exact counting-rank selection on u16 candidates ----
    for (int q = 0; q < 2; q++) {
        const uint16_t* sv = q ? candHi : candLo;
        int n  = min(q ? cHi : cLo, CAP);
        int t0 = (q ? KH : KL) - s_selCum[q ? 2 : 0];
        for (int i = t; i < n; i += TPB2) {
            int v = sv[i];
            int L = 0, E = 0;
            for (int j = 0; j < n; j++) {
                int u = sv[j];
                L += (u < v);
                E += (u == v);
            }
            if (L <= t0     && t0     < L + E) s_res[2 * q]     = v;
            if (L <= t0 + 1 && t0 + 1 < L + E) s_res[2 * q + 1] = v;
        }
    }
    __syncthreads();

    if (t == 0) {
        float loQ = 0.5f * (float)(s_res[0] + s_res[1]);
        float hiQ = 0.5f * (float)(s_res[2] + s_res[3]);
        float rngQ = fmaxf(hiQ - loQ, 1e-6f * QSCALE);
        s_loS  = loQ;
        s_invS = 1.0f / rngQ;
    }
    __syncthreads();

    // ---- phase D: normalize + clip from on-chip values, stream out ----
    const float loS  = s_loS;
    const float invS = s_invS;
    float4* __restrict__ o4 = (float4*)out + (size_t)s * (HW / 4);

#pragma unroll 4
    for (int k = 0; k < SMI; k++) {
        uint32_t p0 = sval[k * TPB2 + t];
        uint32_t p1 = sval[PLANE + k * TPB2 + t];
        float4 r;
        r.x = __saturatef(((float)(p0 & 0xFFFFu) - loS) * invS);
        r.y = __saturatef(((float)(p0 >> 16)     - loS) * invS);
        r.z = __saturatef(((float)(p1 & 0xFFFFu) - loS) * invS);
        r.w = __saturatef(((float)(p1 >> 16)     - loS) * invS);
        __stcs(o4 + k * TPB2 + t, r);
    }
#pragma unroll
    for (int kk = 0; kk < RGI; kk++) {
        uint32_t p0 = rv[2 * kk], p1 = rv[2 * kk + 1];
        float4 r;
        r.x = __saturatef(((float)(p0 & 0xFFFFu) - loS) * invS);
        r.y = __saturatef(((float)(p0 >> 16)     - loS) * invS);
        r.z = __saturatef(((float)(p1 & 0xFFFFu) - loS) * invS);
        r.w = __saturatef(((float)(p1 >> 16)     - loS) * invS);
        __stcs(o4 + (SMI + kk) * TPB2 + t, r);
    }
}

// ---------------- launch ----------------
extern "C" void kernel_launch(void* const* d_in, const int* in_sizes, int n_in,
                              void* d_out, int out_size) {
    const float* x = (const float*)d_in[0];
    float* out = (float*)d_out;

    cudaFuncSetAttribute(k2_select_norm, cudaFuncAttributeMaxDynamicSharedMemorySize, DYN_SMEM);
    k1_quant_hist<<<BATCH * BPS1, TPB1>>>(x);
    k2_select_norm<<<BATCH, TPB2, DYN_SMEM>>>(out);
}

// round 8
// speedup vs baseline: 1.1354x; 1.0261x over previous
#include <cuda_runtime.h>
#include <cstdint>

// ---------------- problem constants ----------------
#define BATCH 256
#define HW    147456            // 384*384 px per sample
#define NB    4096              // coarse histogram bins (bin = q >> 4)
#define QSCALE 65535.0f
#define CAP   2048              // global candidate capacity per quantile

// target order-statistic ranks (0-based): q*(n-1) = 14745.5 / 132709.5
#define KL 14745
#define KH 132709

// K1 geometry: 4 blocks/sample, 1024 threads, 36 px/thread
#define TPB1   1024
#define BPS1   4
#define PXB1   (HW / BPS1)            // 36864 px per block
#define ITER1  (PXB1 / (TPB1 * 4))    // 9 iterations of 4 px

// K3 geometry: 4 blocks/sample, 1024 threads, 9 uint2 (36 px) per thread
#define TPB3   1024
#define BPS3   4
#define W3     (HW / 4 / BPS3 / TPB3) // 9 uint2 per thread

// K5 geometry: 9 blocks/sample, 512 threads, 8 float4 (32 px) per thread
#define TPB5   512
#define F4PT   8
#define PXB5   (TPB5 * F4PT * 4)      // 16384 px per block
#define BPS5   (HW / PXB5)            // 9 blocks per sample

// ---------------- device scratch (static, allocation-free, zero-init) -------
__device__ uint32_t g_xq[BATCH * HW / 2];     // packed u16 means, 75 MB
__device__ int      g_hist[BATCH * NB];       // per-sample hist (self-cleaned by K2)
__device__ uint32_t g_win[BATCH][4];          // qL0, qL1, qH0, qH1 (inclusive u16)
__device__ int      g_cumq[BATCH][2];         // counts before lo/hi windows
__device__ int      g_cnt[BATCH][2];          // candidate counters (self-cleaned by K4)
__device__ uint16_t g_cand[BATCH][2][CAP];
__device__ float2   g_ab[BATCH];              // loQ, invQ

// ---- K1: stream x, channel-mean, quantize u16, write xq, coarse hist -------
__global__ void __launch_bounds__(TPB1) k1_quant_hist(const float* __restrict__ x) {
    __shared__ int sh[NB];
    const int s     = blockIdx.x >> 2;
    const int chunk = blockIdx.x & (BPS1 - 1);
    const int t     = threadIdx.x;

    for (int i = t; i < NB; i += TPB1) sh[i] = 0;
    __syncthreads();

    const int base = s * HW + chunk * PXB1;
    const float4* __restrict__ xin = (const float4*)x;
    const float third = 1.0f / 3.0f;

#pragma unroll 3
    for (int it = 0; it < ITER1; ++it) {
        int p  = base + it * (TPB1 * 4) + t * 4;
        int f4 = (p * 3) >> 2;
        float4 a = __ldcs(xin + f4 + 0);   // stream x: don't pollute L2
        float4 b = __ldcs(xin + f4 + 1);
        float4 c = __ldcs(xin + f4 + 2);

        uint32_t q0 = min((uint32_t)((a.x + a.y + a.z) * third * QSCALE + 0.5f), 65535u);
        uint32_t q1 = min((uint32_t)((a.w + b.x + b.y) * third * QSCALE + 0.5f), 65535u);
        uint32_t q2 = min((uint32_t)((b.z + b.w + c.x) * third * QSCALE + 0.5f), 65535u);
        uint32_t q3 = min((uint32_t)((c.y + c.z + c.w) * third * QSCALE + 0.5f), 65535u);

        uint2 w; w.x = q0 | (q1 << 16); w.y = q2 | (q3 << 16);
        ((uint2*)g_xq)[p >> 2] = w;        // retain in L2 for K3/K5

        atomicAdd(&sh[q0 >> 4], 1);
        atomicAdd(&sh[q1 >> 4], 1);
        atomicAdd(&sh[q2 >> 4], 1);
        atomicAdd(&sh[q3 >> 4], 1);
    }
    __syncthreads();

    int* gh = &g_hist[s * NB];
    for (int i = t; i < NB; i += TPB1) {
        int v = sh[i];
        if (v) atomicAdd(&gh[i], v);
    }
}

// ---- K2: scan hist -> windows + cums, self-clean hist -----------------------
__global__ void __launch_bounds__(1024) k2_scan() {
    __shared__ int s_warp[32];
    const int s = blockIdx.x;
    const int t = threadIdx.x;
    const int lane = t & 31;
    const int wid  = t >> 5;

    int* gh = &g_hist[s * NB];
    int4 cw = *(int4*)(gh + 4 * t);
    *(int4*)(gh + 4 * t) = make_int4(0, 0, 0, 0);   // self-clean for replay
    int cnt[4] = {cw.x, cw.y, cw.z, cw.w};
    int local = cnt[0] + cnt[1] + cnt[2] + cnt[3];

    int v = local;
#pragma unroll
    for (int o = 1; o < 32; o <<= 1) {
        int n = __shfl_up_sync(0xFFFFFFFFu, v, o);
        if (lane >= o) v += n;
    }
    if (lane == 31) s_warp[wid] = v;
    __syncthreads();
    if (wid == 0) {
        int wv = s_warp[lane];
#pragma unroll
        for (int o = 1; o < 32; o <<= 1) {
            int n = __shfl_up_sync(0xFFFFFFFFu, wv, o);
            if (lane >= o) wv += n;
        }
        s_warp[lane] = wv;
    }
    __syncthreads();
    int cum = (v - local) + (wid ? s_warp[wid - 1] : 0);

    const int targets[4] = {KL, KL + 1, KH, KH + 1};
#pragma unroll
    for (int i = 0; i < 4; i++) {
        int c = cnt[i];
        int bin = 4 * t + i;
#pragma unroll
        for (int k = 0; k < 4; k++) {
            int r = targets[k];
            if (cum <= r && r < cum + c) {
                if (k == 0) { g_win[s][0] = (uint32_t)(bin << 4); g_cumq[s][0] = cum; }
                if (k == 1) { g_win[s][1] = (uint32_t)((bin << 4) | 15); }
                if (k == 2) { g_win[s][2] = (uint32_t)(bin << 4); g_cumq[s][1] = cum; }
                if (k == 3) { g_win[s][3] = (uint32_t)((bin << 4) | 15); }
            }
        }
        cum += c;
    }
}

// ---- K3: stream xq (L2-hot), gather window candidates to global ------------
__global__ void __launch_bounds__(TPB3) k3_gather() {
    const int s     = blockIdx.x >> 2;
    const int chunk = blockIdx.x & (BPS3 - 1);
    const int t     = threadIdx.x;

    const uint32_t qL0 = g_win[s][0], qL1 = g_win[s][1];
    const uint32_t qH0 = g_win[s][2], qH1 = g_win[s][3];

    const uint2* __restrict__ xq2 =
        (const uint2*)g_xq + (size_t)s * (HW / 4) + chunk * (TPB3 * W3);

#pragma unroll
    for (int k = 0; k < W3; k++) {
        uint2 w = xq2[k * TPB3 + t];
        uint32_t qs[4] = {w.x & 0xFFFFu, w.x >> 16, w.y & 0xFFFFu, w.y >> 16};
#pragma unroll
        for (int i = 0; i < 4; i++) {
            uint32_t q = qs[i];
            if (q >= qL0 && q <= qL1) {
                int idx = atomicAdd(&g_cnt[s][0], 1);
                if (idx < CAP) g_cand[s][0][idx] = (uint16_t)q;
            }
            if (q >= qH0 && q <= qH1) {
                int idx = atomicAdd(&g_cnt[s][1], 1);
                if (idx < CAP) g_cand[s][1][idx] = (uint16_t)q;
            }
        }
    }
}

// ---- K4: exact counting-rank select on candidates; reset counters ----------
__global__ void __launch_bounds__(256) k4_select() {
    const int s = blockIdx.x;
    const int t = threadIdx.x;
    __shared__ uint16_t sv[CAP];
    __shared__ int s_res[4];

    for (int q = 0; q < 2; q++) {
        int n = min(g_cnt[s][q], CAP);
        for (int i = t; i < n; i += 256) sv[i] = g_cand[s][q][i];
        __syncthreads();

        int t0 = (q ? KH : KL) - g_cumq[s][q];
        for (int i = t; i < n; i += 256) {
            int v = sv[i];
            int L = 0, E = 0;
            for (int j = 0; j < n; j++) {
                int u = sv[j];
                L += (u < v);
                E += (u == v);
            }
            if (L <= t0     && t0     < L + E) s_res[2 * q]     = v;
            if (L <= t0 + 1 && t0 + 1 < L + E) s_res[2 * q + 1] = v;
        }
        __syncthreads();
    }

    if (t == 0) {
        float loQ = 0.5f * (float)(s_res[0] + s_res[1]);
        float hiQ = 0.5f * (float)(s_res[2] + s_res[3]);
        float rngQ = fmaxf(hiQ - loQ, 1e-6f * QSCALE);
        g_ab[s] = make_float2(loQ, 1.0f / rngQ);
        g_cnt[s][0] = 0;                 // self-clean for replay
        g_cnt[s][1] = 0;
    }
}

// ---- K5: normalize + clip; xq read mostly L2-hot, streamed output ----------
__global__ void __launch_bounds__(TPB5) k5_norm(float* __restrict__ out) {
    const int s     = blockIdx.x / BPS5;
    const int chunk = blockIdx.x % BPS5;
    const int t     = threadIdx.x;

    float2 ab = g_ab[s];
    const float loQ  = ab.x;
    const float invQ = ab.y;

    const uint2* __restrict__ xq2 =
        (const uint2*)g_xq + (size_t)s * (HW / 4) + chunk * (TPB5 * F4PT);
    float4* __restrict__ o4 =
        (float4*)out + (size_t)s * (HW / 4) + chunk * (TPB5 * F4PT);

#pragma unroll
    for (int k = 0; k < F4PT; k++) {
        uint2 w = __ldcs(xq2 + k * TPB5 + t);   // last use of xq
        float4 r;
        r.x = __saturatef(((float)(w.x & 0xFFFFu) - loQ) * invQ);
        r.y = __saturatef(((float)(w.x >> 16)     - loQ) * invQ);
        r.z = __saturatef(((float)(w.y & 0xFFFFu) - loQ) * invQ);
        r.w = __saturatef(((float)(w.y >> 16)     - loQ) * invQ);
        __stcs(o4 + k * TPB5 + t, r);
    }
}

// ---------------- launch ----------------
extern "C" void kernel_launch(void* const* d_in, const int* in_sizes, int n_in,
                              void* d_out, int out_size) {
    const float* x = (const float*)d_in[0];
    float* out = (float*)d_out;

    k1_quant_hist<<<BATCH * BPS1, TPB1>>>(x);
    k2_scan<<<BATCH, 1024>>>();
    k3_gather<<<BATCH * BPS3, TPB3>>>();
    k4_select<<<BATCH, 256>>>();
    k5_norm<<<BATCH * BPS5, TPB5>>>(out);
}

// round 9
// speedup vs baseline: 1.1869x; 1.0453x over previous
#include <cuda_runtime.h>
#include <cstdint>

// ---------------- problem constants ----------------
#define BATCH 256
#define HW    147456            // 384*384 px per sample
#define NB    4096              // coarse histogram bins (bin = q >> 4)
#define QSCALE 65535.0f
#define CAP   2048              // candidate capacity per quantile (smem)

// target order-statistic ranks (0-based): q*(n-1) = 14745.5 / 132709.5
#define KL 14745
#define KH 132709

// K1 geometry: 4 blocks/sample, 1024 threads, 36 px/thread
#define TPB1   1024
#define BPS1   4
#define PXB1   (HW / BPS1)            // 36864 px per block
#define ITER1  (PXB1 / (TPB1 * 4))    // 9 iterations of 4 px

// K234 geometry: 1 block/sample, 1024 threads, 36 uint2/thread
#define TPB2   1024
#define W2     (HW / 4 / TPB2)        // 36 uint2 per thread

// K5 geometry: 9 blocks/sample, 512 threads, 8 float4 (32 px) per thread
#define TPB5   512
#define F4PT   8
#define PXB5   (TPB5 * F4PT * 4)      // 16384 px per block
#define BPS5   (HW / PXB5)            // 9 blocks per sample

// ---------------- device scratch (static, allocation-free, zero-init) -------
__device__ uint32_t g_xq[BATCH * HW / 2];     // packed u16 means, 75 MB
__device__ int      g_hist[BATCH * NB];       // per-sample hist (self-cleaned)
__device__ float2   g_ab[BATCH];              // loQ, invQ

// ---- K1: stream x, channel-mean, quantize u16, write xq, coarse hist -------
__global__ void __launch_bounds__(TPB1) k1_quant_hist(const float* __restrict__ x) {
    __shared__ int sh[NB];
    const int s     = blockIdx.x >> 2;
    const int chunk = blockIdx.x & (BPS1 - 1);
    const int t     = threadIdx.x;

    for (int i = t; i < NB; i += TPB1) sh[i] = 0;
    __syncthreads();

    const int base = s * HW + chunk * PXB1;
    const float4* __restrict__ xin = (const float4*)x;
    const float third = 1.0f / 3.0f;

#pragma unroll 3
    for (int it = 0; it < ITER1; ++it) {
        int p  = base + it * (TPB1 * 4) + t * 4;
        int f4 = (p * 3) >> 2;
        float4 a = __ldcs(xin + f4 + 0);   // stream x: don't pollute L2
        float4 b = __ldcs(xin + f4 + 1);
        float4 c = __ldcs(xin + f4 + 2);

        uint32_t q0 = min((uint32_t)((a.x + a.y + a.z) * third * QSCALE + 0.5f), 65535u);
        uint32_t q1 = min((uint32_t)((a.w + b.x + b.y) * third * QSCALE + 0.5f), 65535u);
        uint32_t q2 = min((uint32_t)((b.z + b.w + c.x) * third * QSCALE + 0.5f), 65535u);
        uint32_t q3 = min((uint32_t)((c.y + c.z + c.w) * third * QSCALE + 0.5f), 65535u);

        uint2 w; w.x = q0 | (q1 << 16); w.y = q2 | (q3 << 16);
        ((uint2*)g_xq)[p >> 2] = w;        // retain in L2 for K234/K5

        atomicAdd(&sh[q0 >> 4], 1);
        atomicAdd(&sh[q1 >> 4], 1);
        atomicAdd(&sh[q2 >> 4], 1);
        atomicAdd(&sh[q3 >> 4], 1);
    }
    __syncthreads();

    int* gh = &g_hist[s * NB];
    for (int i = t; i < NB; i += TPB1) {
        int v = sh[i];
        if (v) atomicAdd(&gh[i], v);
    }
}

// ---- K234: scan hist -> windows; gather candidates (L2-hot xq); select -----
__global__ void __launch_bounds__(TPB2) k234(void) {
    __shared__ int s_warp[32];
    __shared__ int s_selBin[4], s_selCum[4];
    __shared__ uint16_t candLo[CAP], candHi[CAP];
    __shared__ int cLo, cHi;
    __shared__ int s_res[4];

    const int s = blockIdx.x;
    const int t = threadIdx.x;
    const int lane = t & 31;
    const int wid  = t >> 5;

    if (t == 0) { cLo = 0; cHi = 0; }

    // ---- phase A: read hist (4 bins/thread int4), self-clean, scan ----
    {
        int* gh = &g_hist[s * NB];
        int4 cw = *(int4*)(gh + 4 * t);
        *(int4*)(gh + 4 * t) = make_int4(0, 0, 0, 0);   // self-clean for replay
        int cnt[4] = {cw.x, cw.y, cw.z, cw.w};
        int local = cnt[0] + cnt[1] + cnt[2] + cnt[3];

        int v = local;
#pragma unroll
        for (int o = 1; o < 32; o <<= 1) {
            int n = __shfl_up_sync(0xFFFFFFFFu, v, o);
            if (lane >= o) v += n;
        }
        if (lane == 31) s_warp[wid] = v;
        __syncthreads();
        if (wid == 0) {
            int wv = s_warp[lane];
#pragma unroll
            for (int o = 1; o < 32; o <<= 1) {
                int n = __shfl_up_sync(0xFFFFFFFFu, wv, o);
                if (lane >= o) wv += n;
            }
            s_warp[lane] = wv;
        }
        __syncthreads();
        int cum = (v - local) + (wid ? s_warp[wid - 1] : 0);

        const int targets[4] = {KL, KL + 1, KH, KH + 1};
#pragma unroll
        for (int i = 0; i < 4; i++) {
            int c = cnt[i];
#pragma unroll
            for (int k = 0; k < 4; k++) {
                int r = targets[k];
                if (cum <= r && r < cum + c) { s_selBin[k] = 4 * t + i; s_selCum[k] = cum; }
            }
            cum += c;
        }
    }
    __syncthreads();

    // u16 gather windows (inclusive)
    const uint32_t qL0 = (uint32_t)(s_selBin[0] << 4);
    const uint32_t qL1 = (uint32_t)((s_selBin[1] << 4) | 15);
    const uint32_t qH0 = (uint32_t)(s_selBin[2] << 4);
    const uint32_t qH1 = (uint32_t)((s_selBin[3] << 4) | 15);

    // ---- phase B: stream xq (L2-hot), gather window hits to smem ----
    const uint2* __restrict__ xq2 = (const uint2*)g_xq + (size_t)s * (HW / 4);
#pragma unroll 4
    for (int k = 0; k < W2; k++) {
        uint2 w = xq2[k * TPB2 + t];
        uint32_t qs[4] = {w.x & 0xFFFFu, w.x >> 16, w.y & 0xFFFFu, w.y >> 16};
#pragma unroll
        for (int i = 0; i < 4; i++) {
            uint32_t q = qs[i];
            if (q >= qL0 && q <= qL1) {
                int idx = atomicAdd(&cLo, 1);
                if (idx < CAP) candLo[idx] = (uint16_t)q;
            }
            if (q >= qH0 && q <= qH1) {
                int idx = atomicAdd(&cHi, 1);
                if (idx < CAP) candHi[idx] = (uint16_t)q;
            }
        }
    }
    __syncthreads();

    // ---- phase C: exact counting-rank selection on u16 candidates ----
    for (int q = 0; q < 2; q++) {
        const uint16_t* sv = q ? candHi : candLo;
        int n  = min(q ? cHi : cLo, CAP);
        int t0 = (q ? KH : KL) - s_selCum[q ? 2 : 0];
        for (int i = t; i < n; i += TPB2) {
            int v = sv[i];
            int L = 0, E = 0;
            for (int j = 0; j < n; j++) {
                int u = sv[j];
                L += (u < v);
                E += (u == v);
            }
            if (L <= t0     && t0     < L + E) s_res[2 * q]     = v;
            if (L <= t0 + 1 && t0 + 1 < L + E) s_res[2 * q + 1] = v;
        }
    }
    __syncthreads();

    if (t == 0) {
        float loQ = 0.5f * (float)(s_res[0] + s_res[1]);
        float hiQ = 0.5f * (float)(s_res[2] + s_res[3]);
        float rngQ = fmaxf(hiQ - loQ, 1e-6f * QSCALE);
        g_ab[s] = make_float2(loQ, 1.0f / rngQ);
    }
}

// ---- K5: normalize + clip; xq read mostly L2-hot, streamed output ----------
__global__ void __launch_bounds__(TPB5) k5_norm(float* __restrict__ out) {
    const int s     = blockIdx.x / BPS5;
    const int chunk = blockIdx.x % BPS5;
    const int t     = threadIdx.x;

    float2 ab = g_ab[s];
    const float loQ  = ab.x;
    const float invQ = ab.y;

    const uint2* __restrict__ xq2 =
        (const uint2*)g_xq + (size_t)s * (HW / 4) + chunk * (TPB5 * F4PT);
    float4* __restrict__ o4 =
        (float4*)out + (size_t)s * (HW / 4) + chunk * (TPB5 * F4PT);

#pragma unroll
    for (int k = 0; k < F4PT; k++) {
        uint2 w = __ldcs(xq2 + k * TPB5 + t);   // last use of xq
        float4 r;
        r.x = __saturatef(((float)(w.x & 0xFFFFu) - loQ) * invQ);
        r.y = __saturatef(((float)(w.x >> 16)     - loQ) * invQ);
        r.z = __saturatef(((float)(w.y & 0xFFFFu) - loQ) * invQ);
        r.w = __saturatef(((float)(w.y >> 16)     - loQ) * invQ);
        __stcs(o4 + k * TPB5 + t, r);
    }
}

// ---------------- launch ----------------
extern "C" void kernel_launch(void* const* d_in, const int* in_sizes, int n_in,
                              void* d_out, int out_size) {
    const float* x = (const float*)d_in[0];
    float* out = (float*)d_out;

    k1_quant_hist<<<BATCH * BPS1, TPB1>>>(x);
    k234<<<BATCH, TPB2>>>();
    k5_norm<<<BATCH * BPS5, TPB5>>>(out);
}